// round 1
// baseline (speedup 1.0000x reference)
#include <cuda_runtime.h>

#define BB 16
#define SS 4096
#define DD 1024
#define ND 14
#define D4 (DD/4)          // 256 float4 per row
#define S_CHUNKS 32
#define S_PER (SS/S_CHUNKS) // 128 rows per pooling CTA

// Scratch (device globals — no allocation allowed)
__device__ float g_pooled[BB*DD];   // sum over S (not yet divided)
__device__ float g_ahat[BB*ND];
__device__ float g_R[BB*DD];

// ---------------------------------------------------------------------------
__global__ void zero_pooled_kernel() {
    int i = blockIdx.x * blockDim.x + threadIdx.x;
    if (i < BB*DD) g_pooled[i] = 0.0f;
}

// ---------------------------------------------------------------------------
// Sum z_fused over S. grid = BB*S_CHUNKS blocks, 256 threads.
// Thread t owns float4 column d4=t; loops over its 128 S-rows (coalesced).
__global__ void pool_kernel(const float* __restrict__ z) {
    int b  = blockIdx.x / S_CHUNKS;
    int sc = blockIdx.x % S_CHUNKS;
    int d4 = threadIdx.x;

    const float4* zp = reinterpret_cast<const float4*>(z)
                     + ((size_t)b * SS + (size_t)sc * S_PER) * D4 + d4;

    float4 acc = make_float4(0.f, 0.f, 0.f, 0.f);
#pragma unroll 8
    for (int s = 0; s < S_PER; ++s) {
        float4 v = zp[(size_t)s * D4];
        acc.x += v.x; acc.y += v.y; acc.z += v.z; acc.w += v.w;
    }
    float* p = &g_pooled[b * DD + d4 * 4];
    atomicAdd(p + 0, acc.x);
    atomicAdd(p + 1, acc.y);
    atomicAdd(p + 2, acc.z);
    atomicAdd(p + 3, acc.w);
}

// ---------------------------------------------------------------------------
// Per (b,n): dots with M[n,0,:] and M[n,1,:], softmax over 2 states,
// write mlc_probs (into d_out tail) and alpha_hat scratch.
// grid = BB*ND blocks, 128 threads.
__global__ void score_kernel(const float* __restrict__ M,
                             float* __restrict__ mlc_out) {
    int b = blockIdx.x / ND;
    int n = blockIdx.x % ND;
    int tid = threadIdx.x;

    const float* zp = &g_pooled[b * DD];
    const float* m0 = &M[(n * 2 + 0) * DD];
    const float* m1 = &M[(n * 2 + 1) * DD];

    float s0 = 0.f, s1 = 0.f;
    for (int i = tid; i < DD; i += 128) {
        float zv = zp[i];
        s0 = fmaf(zv, m0[i], s0);
        s1 = fmaf(zv, m1[i], s1);
    }
#pragma unroll
    for (int off = 16; off > 0; off >>= 1) {
        s0 += __shfl_down_sync(0xffffffffu, s0, off);
        s1 += __shfl_down_sync(0xffffffffu, s1, off);
    }
    __shared__ float sh0[4], sh1[4];
    int w = tid >> 5;
    if ((tid & 31) == 0) { sh0[w] = s0; sh1[w] = s1; }
    __syncthreads();
    if (tid == 0) {
        float t0 = sh0[0] + sh0[1] + sh0[2] + sh0[3];
        float t1 = sh1[0] + sh1[1] + sh1[2] + sh1[3];
        // pooled holds SUM over S; scores = (sum/S) dot M / sqrt(D)
        float diff = (t1 - t0) * (1.0f / (4096.0f * 32.0f));
        float p1 = 1.0f / (1.0f + expf(-diff));   // softmax over 2 states
        mlc_out[b * ND + n] = p1;
        g_ahat[b * ND + n] = (p1 > 0.2f) ? 1.0f : 0.0f;
    }
}

// ---------------------------------------------------------------------------
// R[b,:] = sum_n ahat[b,n] * M[n,1,:].  grid = BB blocks, 256 threads (float4).
__global__ void r_kernel(const float* __restrict__ M) {
    int b  = blockIdx.x;
    int d4 = threadIdx.x;
    float4 acc = make_float4(0.f, 0.f, 0.f, 0.f);
#pragma unroll
    for (int n = 0; n < ND; ++n) {
        float a = g_ahat[b * ND + n];
        float4 m = reinterpret_cast<const float4*>(M + (size_t)(n * 2 + 1) * DD)[d4];
        acc.x += a * m.x; acc.y += a * m.y; acc.z += a * m.z; acc.w += a * m.w;
    }
    reinterpret_cast<float4*>(g_R)[b * D4 + d4] = acc;
}

// ---------------------------------------------------------------------------
// z_out = z_fused + R[b,:] broadcast over S.  Pure stream add.
// grid = B*S*D/4/256 = 65536 blocks, 256 threads, 1 float4 per thread.
__global__ void add_kernel(const float* __restrict__ z,
                           float* __restrict__ out) {
    long long i = (long long)blockIdx.x * blockDim.x + threadIdx.x; // float4 idx
    int d4 = (int)(i & (D4 - 1));
    int b  = (int)(i >> 20);        // S*D4 = 4096*256 = 2^20 float4 per batch
    float4 v = reinterpret_cast<const float4*>(z)[i];
    float4 r = reinterpret_cast<const float4*>(g_R)[(b << 8) + d4];
    v.x += r.x; v.y += r.y; v.z += r.z; v.w += r.w;
    reinterpret_cast<float4*>(out)[i] = v;
}

// ---------------------------------------------------------------------------
extern "C" void kernel_launch(void* const* d_in, const int* in_sizes, int n_in,
                              void* d_out, int out_size) {
    const float* z = (const float*)d_in[0];   // z_fused (16,4096,1024)
    const float* M = (const float*)d_in[1];   // M (14,2,1024)
    float* out = (float*)d_out;               // [z_out | mlc_probs]
    float* mlc = out + (size_t)BB * SS * DD;

    zero_pooled_kernel<<<(BB*DD + 255) / 256, 256>>>();
    pool_kernel<<<BB * S_CHUNKS, 256>>>(z);
    score_kernel<<<BB * ND, 128>>>(M, mlc);
    r_kernel<<<BB, 256>>>(M);
    add_kernel<<<(BB * (long long)SS * DD / 4) / 256, 256>>>(z, out);
}

// round 2
// speedup vs baseline: 1.0657x; 1.0657x over previous
#include <cuda_runtime.h>

#define BB 16
#define SS 4096
#define DD 1024
#define ND 14
#define D4 (DD/4)            // 256 float4 per row
#define S_CHUNKS 64
#define S_PER (SS/S_CHUNKS)  // 64 rows per pooling CTA

// Scratch (device globals — allocation is forbidden)
__device__ float g_partial[S_CHUNKS * BB * DD];  // 4 MB of per-chunk partial sums
__device__ float g_R[BB * DD];

// ---------------------------------------------------------------------------
// Partial sums over S, no atomics (so no zero-pass needed).
// grid = BB*S_CHUNKS = 1024 CTAs, 256 threads. Thread t owns float4 column t,
// sums its 64 rows, writes one float4 partial.
__global__ void pool_kernel(const float* __restrict__ z) {
    int b  = blockIdx.x / S_CHUNKS;
    int sc = blockIdx.x % S_CHUNKS;
    int d4 = threadIdx.x;

    const float4* zp = reinterpret_cast<const float4*>(z)
                     + ((size_t)b * SS + (size_t)sc * S_PER) * D4 + d4;

    float4 acc = make_float4(0.f, 0.f, 0.f, 0.f);
#pragma unroll 8
    for (int s = 0; s < S_PER; ++s) {
        float4 v = zp[(size_t)s * D4];
        acc.x += v.x; acc.y += v.y; acc.z += v.z; acc.w += v.w;
    }
    reinterpret_cast<float4*>(g_partial)[((size_t)sc * BB + b) * D4 + d4] = acc;
}

// ---------------------------------------------------------------------------
// Fused middle stage: reduce partials -> 28 dots -> softmax/threshold -> R.
// grid = BB = 16 CTAs, 1024 threads.
__global__ void mid_kernel(const float* __restrict__ M,
                           float* __restrict__ mlc_out) {
    int b   = blockIdx.x;
    int tid = threadIdx.x;

    __shared__ float sh_pooled[DD];
    __shared__ float sh_dot[2 * ND];
    __shared__ float sh_ahat[ND];

    // 1) reduce the 64 chunk-partials for this b (reads hit L2; 256 KB/block)
    float acc = 0.f;
#pragma unroll 8
    for (int sc = 0; sc < S_CHUNKS; ++sc)
        acc += g_partial[((size_t)sc * BB + b) * DD + tid];
    sh_pooled[tid] = acc;
    __syncthreads();

    // 2) 28 dots: warp w handles (n = w/2, s = w&1)
    int w = tid >> 5, lane = tid & 31;
    if (w < 2 * ND) {
        const float* m = &M[(size_t)w * DD];   // M is [ND][2][DD], w = n*2+s
        float d = 0.f;
#pragma unroll 8
        for (int i = lane; i < DD; i += 32)
            d = fmaf(sh_pooled[i], m[i], d);
#pragma unroll
        for (int off = 16; off > 0; off >>= 1)
            d += __shfl_down_sync(0xffffffffu, d, off);
        if (lane == 0) sh_dot[w] = d;
    }
    __syncthreads();

    // 3) softmax over 2 states == sigmoid of score diff; threshold
    if (tid < ND) {
        // sh_dot holds SUM-over-S dots; scores = (sum/S) dot / sqrt(D)
        float diff = (sh_dot[2 * tid + 1] - sh_dot[2 * tid]) * (1.0f / (4096.0f * 32.0f));
        float p1 = 1.0f / (1.0f + expf(-diff));
        mlc_out[b * ND + tid] = p1;
        sh_ahat[tid] = (p1 > 0.2f) ? 1.0f : 0.0f;
    }
    __syncthreads();

    // 4) R[b, tid] = sum_n ahat[n] * M[n,1,tid]   (M rows hot in L2)
    float r = 0.f;
#pragma unroll
    for (int n = 0; n < ND; ++n)
        r = fmaf(sh_ahat[n], M[(size_t)(n * 2 + 1) * DD + tid], r);
    g_R[b * DD + tid] = r;
}

// ---------------------------------------------------------------------------
// z_out = z_fused + R broadcast. REVERSED block order: pool left the tail of
// z resident in L2, so add reads that tail first and hits L2. Streaming hints
// (__ldcs/__stcs) keep this one-shot traffic from evicting the reusable lines.
__global__ void add_kernel(const float* __restrict__ z,
                           float* __restrict__ out) {
    long long bi = (long long)(gridDim.x - 1 - blockIdx.x);       // reversed
    long long i  = bi * blockDim.x + threadIdx.x;                 // float4 idx
    int d4 = (int)(i & (D4 - 1));
    int b  = (int)(i >> 20);        // S*D4 = 2^20 float4 per batch

    float4 v = __ldcs(reinterpret_cast<const float4*>(z) + i);
    float4 r = reinterpret_cast<const float4*>(g_R)[(b << 8) + d4];
    v.x += r.x; v.y += r.y; v.z += r.z; v.w += r.w;
    __stcs(reinterpret_cast<float4*>(out) + i, v);
}

// ---------------------------------------------------------------------------
extern "C" void kernel_launch(void* const* d_in, const int* in_sizes, int n_in,
                              void* d_out, int out_size) {
    const float* z = (const float*)d_in[0];   // z_fused (16,4096,1024)
    const float* M = (const float*)d_in[1];   // M (14,2,1024)
    float* out = (float*)d_out;               // [z_out | mlc_probs]
    float* mlc = out + (size_t)BB * SS * DD;

    pool_kernel<<<BB * S_CHUNKS, 256>>>(z);
    mid_kernel<<<BB, 1024>>>(M, mlc);
    add_kernel<<<(int)(((long long)BB * SS * DD / 4) / 256), 256>>>(z, out);
}